// round 7
// baseline (speedup 1.0000x reference)
#include <cuda_runtime.h>
#include <cuda_bf16.h>
#include <math.h>

#define FULLMASK 0xffffffffu
#define SWAPF(a,b) { float _t=(a); (a)=(b); (b)=_t; }

constexpr int T_ = 128;
constexpr int H_ = 128;
constexpr float EPS_ = 1e-5f;
constexpr float R2_ = 0.70710678118654752440f;

__device__ float g_emb[1024 * 128 * 128];   // LN(emb)+pe
__device__ float g_pj[1024 * 128 * 8];      // emb-half of proj dot, ip_b folded in

__device__ __forceinline__ float warp_sum(float v) {
    v += __shfl_xor_sync(FULLMASK, v, 16);
    v += __shfl_xor_sync(FULLMASK, v, 8);
    v += __shfl_xor_sync(FULLMASK, v, 4);
    v += __shfl_xor_sync(FULLMASK, v, 2);
    v += __shfl_xor_sync(FULLMASK, v, 1);
    return v;
}
__device__ __forceinline__ float sigf(float x)  { return 1.f / (1.f + __expf(-x)); }
__device__ __forceinline__ float tanhff(float x){ return 1.f - 2.f / (1.f + __expf(2.f * x)); }

// ---------------- kernel 1: fused embeddings + emb-half proj dot ----------------
__global__ __launch_bounds__(128)
void emb_pj_kernel(const float* __restrict__ x, const float* __restrict__ pe,
                   const float* __restrict__ emb_w, const float* __restrict__ emb_b,
                   const float* __restrict__ emb_g, const float* __restrict__ emb_bt,
                   const float* __restrict__ ip_w,  const float* __restrict__ ip_b)
{
    const int e = blockIdx.x, tid = threadIdx.x, w = tid >> 5, lane = tid & 31;
    __shared__ __align__(16) float sx[T_ * 8];
    __shared__ __align__(16) float sipw[8][128];
    __shared__ float sipb[8];

    const float4* xg = (const float4*)(x + (size_t)e * T_ * 8);
    ((float4*)sx)[tid] = xg[tid];
    ((float4*)sx)[tid + 128] = xg[tid + 128];
    #pragma unroll
    for (int i = tid; i < 1024; i += 128)
        sipw[i >> 7][i & 127] = ip_w[(i >> 7) * 256 + (i & 127)];
    if (tid < 8) sipb[tid] = ip_b[tid];

    float ew[4][8], gb[4], bt[4], bb[4];
    #pragma unroll
    for (int m = 0; m < 4; m++) {
        int h = lane + 32 * m;
        #pragma unroll
        for (int k = 0; k < 8; k++) ew[m][k] = emb_w[h * 8 + k];
        gb[m] = emb_g[h]; bt[m] = emb_bt[h]; bb[m] = emb_b[h];
    }
    __syncthreads();
    for (int it = 0; it < 32; it++) {
        int t = it * 4 + w;
        const float* xr = sx + t * 8;
        float e4[4];
        #pragma unroll
        for (int m = 0; m < 4; m++) {
            float s = bb[m];
            #pragma unroll
            for (int k = 0; k < 8; k++) s += xr[k] * ew[m][k];
            e4[m] = s;
        }
        float s = (e4[0]+e4[1])+(e4[2]+e4[3]);
        float q = (e4[0]*e4[0]+e4[1]*e4[1])+(e4[2]*e4[2]+e4[3]*e4[3]);
        s = warp_sum(s); q = warp_sum(q);
        float m_ = s * (1.f/128.f);
        float inv = rsqrtf(q * (1.f/128.f) - m_*m_ + EPS_);
        float val[4];
        #pragma unroll
        for (int m = 0; m < 4; m++) {
            int h = lane + 32 * m;
            val[m] = (e4[m]-m_)*inv*gb[m] + bt[m] + __ldg(pe + t*H_ + h);
            g_emb[(size_t)e*T_*H_ + t*H_ + h] = val[m];
        }
        float d[8];
        #pragma unroll
        for (int jj = 0; jj < 8; jj++) {
            float dv = 0.f;
            #pragma unroll
            for (int m = 0; m < 4; m++) dv += val[m] * sipw[jj][lane + 32*m];
            d[jj] = warp_sum(dv);
        }
        if (lane == 0) {
            float* gp = g_pj + ((size_t)e*T_ + t) * 8;
            ((float4*)gp)[0] = make_float4(d[0]+sipb[0], d[1]+sipb[1], d[2]+sipb[2], d[3]+sipb[3]);
            ((float4*)gp)[1] = make_float4(d[4]+sipb[4], d[5]+sipb[5], d[6]+sipb[6], d[7]+sipb[7]);
        }
    }
}

// ---------------- kernel 2: recurrence. 1 elem/CTA, 64 threads, P=16 ----------------
__global__ __launch_bounds__(64, 7)
void qlstm_kernel(
    const float* __restrict__ ip_w,
    const float* __restrict__ in_g,  const float* __restrict__ in_b,
    const float* __restrict__ wq_i,  const float* __restrict__ wq_f,
    const float* __restrict__ wq_g,  const float* __restrict__ wq_o,
    const float* __restrict__ pi_w,  const float* __restrict__ pi_b,
    const float* __restrict__ pf_w,  const float* __restrict__ pf_b,
    const float* __restrict__ pg_w,  const float* __restrict__ pg_b,
    const float* __restrict__ po_w,  const float* __restrict__ po_b,
    const float* __restrict__ on_g,  const float* __restrict__ on_b,
    const float* __restrict__ out_w, const float* __restrict__ out_b,
    float* __restrict__ out)
{
    const int e = blockIdx.x;
    const int tid = threadIdx.x, w = tid >> 5, lane = tid & 31;
    const int ll = lane & 15, g2 = lane >> 4;
    const int gate = 2 * w + g2;

    __shared__ __align__(16) float  sh_hs[128];
    __shared__ __align__(16) float2 sh_wcs[4][4][8];
    __shared__ __align__(16) float2 sh_incs[8];
    __shared__ __align__(16) float4 sh_pj4[2];     // [warp] -> rows 4w..4w+3
    __shared__ __align__(16) float4 sh_z[4][2];
    __shared__ __align__(16) float4 sh_red[2];
    __shared__ float sh_sc[2], sh_ing8[8], sh_inb8[8];

    // ---- staging ----
    {
        const float* wq[4] = {wq_i, wq_f, wq_g, wq_o};
        #pragma unroll
        for (int i = tid; i < 128; i += 64) {
            int g = i >> 5, rem = i & 31, lyr = rem >> 3, q = rem & 7;
            float a = 0.5f * wq[g][lyr * 8 + q];
            sh_wcs[g][lyr][q] = make_float2(cosf(a), sinf(a));
        }
    }
    if (tid < 8) { sh_ing8[tid] = in_g[tid]; sh_inb8[tid] = in_b[tid]; }

    // Phase-B weights: warp w covers proj rows 4w..4w+3 (h-half of ip_w)
    float wbr[4][4];
    #pragma unroll
    for (int jj = 0; jj < 4; jj++)
        #pragma unroll
        for (int i = 0; i < 4; i++)
            wbr[jj][i] = ip_w[(4*w + jj) * 256 + 128 + lane + 32*i];

    // Phase-D gate weights + biases for h0 = tid, h1 = tid + 64
    float pwr[2][32];
    float bia[2][4];
    {
        const float* pw[4] = {pi_w, pf_w, pg_w, po_w};
        const float* pb[4] = {pi_b, pf_b, pg_b, po_b};
        #pragma unroll
        for (int hh = 0; hh < 2; hh++) {
            int h = tid + 64 * hh;
            #pragma unroll
            for (int g = 0; g < 4; g++) {
                bia[hh][g] = pb[g][h];
                #pragma unroll
                for (int q = 0; q < 8; q++) pwr[hh][g*8+q] = pw[g][h*8+q];
            }
        }
    }
    float gw0 = on_g[tid]*out_w[tid],       gw1 = on_g[tid+64]*out_w[tid+64];
    float bw0 = on_b[tid]*out_w[tid],       bw1 = on_b[tid+64]*out_w[tid+64];
    {
        float s1 = warp_sum(gw0 + gw1), s2 = warp_sum(bw0 + bw1);
        if (lane == 0) sh_red[w] = make_float4(s1, s2, 0.f, 0.f);
    }
    __syncthreads();
    if (tid == 0) {
        sh_sc[0] = sh_red[0].x + sh_red[1].x;
        sh_sc[1] = sh_red[0].y + sh_red[1].y + out_b[0];
    }
    __syncthreads();
    const float S1 = sh_sc[0], C0 = sh_sc[1];

    // fused lane perm (c0: l2^=l3, c2: l0^=l1, then c1: l1^=l2')
    const int psrc = (((ll ^ (ll >> 1) ^ ((ll >> 2) & 1)) & 15)) | (lane & 16);
    const bool c3p = (lane & 1);

    float h_c[2] = {0.f, 0.f}, c_c[2] = {0.f, 0.f};
    const float* embrow = g_emb + (size_t)e * T_ * H_;
    const float* pjrow  = g_pj  + (size_t)e * T_ * 8;

    for (int t = 0; t < T_; t++) {
        sh_hs[tid] = h_c[0]; sh_hs[tid + 64] = h_c[1];
        float emb0 = __ldg(embrow + t * H_ + tid);
        float emb1 = __ldg(embrow + t * H_ + tid + 64);
        __syncthreads();

        // ---- Phase B: h-half dots for rows 4w..4w+3 ----
        {
            float d0 = 0.f, d1 = 0.f, d2 = 0.f, d3 = 0.f;
            #pragma unroll
            for (int i = 0; i < 4; i++) {
                float hv = sh_hs[lane + 32 * i];
                d0 += hv * wbr[0][i]; d1 += hv * wbr[1][i];
                d2 += hv * wbr[2][i]; d3 += hv * wbr[3][i];
            }
            d0 = warp_sum(d0); d1 = warp_sum(d1);
            d2 = warp_sum(d2); d3 = warp_sum(d3);
            if (lane == 0) {
                float4 gp = __ldg((const float4*)(pjrow + t * 8) + w);
                sh_pj4[w] = make_float4(d0 + gp.x, d1 + gp.y, d2 + gp.z, d3 + gp.w);
            }
        }
        __syncthreads();

        // ---- mini-LN(8) + input angles (warp 0; 8-lane groups duplicated) ----
        if (w == 0) {
            int q = lane & 7;
            float pv = tanhff(((const float*)sh_pj4)[q]);
            float sm = pv, sq = pv*pv;
            sm += __shfl_xor_sync(FULLMASK, sm, 1); sq += __shfl_xor_sync(FULLMASK, sq, 1);
            sm += __shfl_xor_sync(FULLMASK, sm, 2); sq += __shfl_xor_sync(FULLMASK, sq, 2);
            sm += __shfl_xor_sync(FULLMASK, sm, 4); sq += __shfl_xor_sync(FULLMASK, sq, 4);
            float mm = sm * 0.125f;
            float iv = rsqrtf(sq * 0.125f - mm*mm + EPS_);
            float a = 0.5f * ((pv - mm) * iv * sh_ing8[q] + sh_inb8[q]);
            if (lane < 8) {
                float ss, cc; __sincosf(a, &ss, &cc);
                sh_incs[q] = make_float2(cc, ss);
            }
        }
        __syncthreads();

        // ---- Phase C: VQC. lane bits(3..0)=qubits(0..3); reg bits(3..0)=qubits(4..7) ----
        float st[16];
        {
            float F0[8], F1[8];
            #pragma unroll
            for (int q = 0; q < 8; q++) {
                float2 cs = sh_incs[q];
                F0[q] = R2_ * (cs.x - cs.y); F1[q] = R2_ * (cs.x + cs.y);
            }
            st[0] = ((ll&8)?F1[0]:F0[0]) * ((ll&4)?F1[1]:F0[1])
                  * ((ll&2)?F1[2]:F0[2]) * ((ll&1)?F1[3]:F0[3]);
            #pragma unroll
            for (int q = 4; q < 8; q++) {
                int s = 1 << (7 - q);
                #pragma unroll
                for (int r = 0; r < 16; r += 2*s) {
                    float v = st[r];
                    st[r] = v * F0[q]; st[r+s] = v * F1[q];
                }
            }
        }

        #pragma unroll
        for (int lyr = 0; lyr < 4; lyr++) {
            // c=4: reg b3 -> flip reg b2
            #pragma unroll
            for (int r = 8; r < 12; r++) SWAPF(st[r], st[r+4]);
            // c=6: reg b1 -> flip reg b0
            #pragma unroll
            for (int r = 2; r < 16; r += 4) SWAPF(st[r], st[r+1]);
            // fused lane perm: c0, c2, c1
            #pragma unroll
            for (int r = 0; r < 16; r++) st[r] = __shfl_sync(FULLMASK, st[r], psrc);
            // c=5: reg b2 -> flip reg b1
            #pragma unroll
            for (int r = 4; r < 16; r += 8) { SWAPF(st[r], st[r+2]); SWAPF(st[r+1], st[r+3]); }
            // c=3: lane b0 -> flip reg b3
            #pragma unroll
            for (int r = 0; r < 8; r++) {
                float a = st[r], b2 = st[r+8];
                st[r] = c3p ? b2 : a; st[r+8] = c3p ? a : b2;
            }

            // RY lane qubits q0..q3 (masks 8,4,2,1)
            #pragma unroll
            for (int q = 0; q < 4; q++) {
                const int bm = 8 >> q;
                float2 cs = sh_wcs[gate][lyr][q];
                float sgn = (lane & bm) ? cs.y : -cs.y;
                #pragma unroll
                for (int r = 0; r < 16; r++) {
                    float o = __shfl_xor_sync(FULLMASK, st[r], bm);
                    st[r] = fmaf(sgn, o, cs.x * st[r]);
                }
            }
            // RY reg qubits q4..q7
            #pragma unroll
            for (int q = 4; q < 8; q++) {
                const int s = 1 << (7 - q);
                float2 cs = sh_wcs[gate][lyr][q];
                #pragma unroll
                for (int r = 0; r < 16; r++) if (!(r & s)) {
                    float a0 = st[r], a1 = st[r+s];
                    st[r] = cs.x*a0 - cs.y*a1; st[r+s] = cs.y*a0 + cs.x*a1;
                }
            }
        }

        // ---- measurement ----
        {
            float p[16];
            #pragma unroll
            for (int r = 0; r < 16; r++) p[r] = st[r]*st[r];
            float s8[8], s4[4], s2[2];
            float z7=0, z6=0, z5=0;
            #pragma unroll
            for (int k = 0; k < 8; k++) { s8[k] = p[2*k]+p[2*k+1]; z7 += p[2*k]-p[2*k+1]; }
            #pragma unroll
            for (int k = 0; k < 4; k++) { s4[k] = s8[2*k]+s8[2*k+1]; z6 += s8[2*k]-s8[2*k+1]; }
            #pragma unroll
            for (int k = 0; k < 2; k++) { s2[k] = s4[2*k]+s4[2*k+1]; z5 += s4[2*k]-s4[2*k+1]; }
            float z4 = s2[0]-s2[1], Tt = s2[0]+s2[1];
            float o, z0v, z1v, z2v, z3v;

            o = __shfl_xor_sync(FULLMASK, Tt, 1);
            z3v = (lane & 1) ? (o - Tt) : (Tt - o); Tt += o;
            z4 += __shfl_xor_sync(FULLMASK, z4, 1);
            z5 += __shfl_xor_sync(FULLMASK, z5, 1);
            z6 += __shfl_xor_sync(FULLMASK, z6, 1);
            z7 += __shfl_xor_sync(FULLMASK, z7, 1);

            o = __shfl_xor_sync(FULLMASK, Tt, 2);
            z2v = (lane & 2) ? (o - Tt) : (Tt - o); Tt += o;
            z3v += __shfl_xor_sync(FULLMASK, z3v, 2);
            z4 += __shfl_xor_sync(FULLMASK, z4, 2);
            z5 += __shfl_xor_sync(FULLMASK, z5, 2);
            z6 += __shfl_xor_sync(FULLMASK, z6, 2);
            z7 += __shfl_xor_sync(FULLMASK, z7, 2);

            o = __shfl_xor_sync(FULLMASK, Tt, 4);
            z1v = (lane & 4) ? (o - Tt) : (Tt - o); Tt += o;
            z2v += __shfl_xor_sync(FULLMASK, z2v, 4);
            z3v += __shfl_xor_sync(FULLMASK, z3v, 4);
            z4 += __shfl_xor_sync(FULLMASK, z4, 4);
            z5 += __shfl_xor_sync(FULLMASK, z5, 4);
            z6 += __shfl_xor_sync(FULLMASK, z6, 4);
            z7 += __shfl_xor_sync(FULLMASK, z7, 4);

            o = __shfl_xor_sync(FULLMASK, Tt, 8);
            z0v = (lane & 8) ? (o - Tt) : (Tt - o);
            z1v += __shfl_xor_sync(FULLMASK, z1v, 8);
            z2v += __shfl_xor_sync(FULLMASK, z2v, 8);
            z3v += __shfl_xor_sync(FULLMASK, z3v, 8);
            z4 += __shfl_xor_sync(FULLMASK, z4, 8);
            z5 += __shfl_xor_sync(FULLMASK, z5, 8);
            z6 += __shfl_xor_sync(FULLMASK, z6, 8);
            z7 += __shfl_xor_sync(FULLMASK, z7, 8);

            if (ll == 0) {
                sh_z[gate][0] = make_float4(z0v, z1v, z2v, z3v);
                sh_z[gate][1] = make_float4(z4, z5, z6, z7);
            }
        }
        __syncthreads();

        // ---- Phase D: gates, LSTM update, output LN ----
        {
            float4 zr[4][2];
            #pragma unroll
            for (int g = 0; g < 4; g++) { zr[g][0] = sh_z[g][0]; zr[g][1] = sh_z[g][1]; }
            float v[2];
            #pragma unroll
            for (int hh = 0; hh < 2; hh++) {
                float pre[4];
                #pragma unroll
                for (int g = 0; g < 4; g++) {
                    float4 z0 = zr[g][0], z1 = zr[g][1];
                    const float* pw = &pwr[hh][g*8];
                    pre[g] = bia[hh][g]
                           + z0.x*pw[0] + z0.y*pw[1] + z0.z*pw[2] + z0.w*pw[3]
                           + z1.x*pw[4] + z1.y*pw[5] + z1.z*pw[6] + z1.w*pw[7];
                }
                float i_t = sigf(pre[0]);
                float f_t = sigf(pre[1]);
                float g_t = tanhff(pre[2]);
                float o_t = sigf(pre[3]);
                c_c[hh] = f_t*c_c[hh] + i_t*g_t;
                h_c[hh] = o_t*tanhff(c_c[hh]);
                v[hh] = h_c[hh] + (hh ? emb1 : emb0);
            }
            float r0 = warp_sum(v[0] + v[1]);
            float r1 = warp_sum(v[0]*v[0] + v[1]*v[1]);
            float r2 = warp_sum(v[0]*gw0 + v[1]*gw1);
            if (lane == 0) sh_red[w] = make_float4(r0, r1, r2, 0.f);
        }
        __syncthreads();
        if (tid == 0) {
            float Sv = sh_red[0].x + sh_red[1].x;
            float Sq = sh_red[0].y + sh_red[1].y;
            float Sg = sh_red[0].z + sh_red[1].z;
            float m2 = Sv * (1.f/128.f);
            float inv2 = rsqrtf(Sq * (1.f/128.f) - m2*m2 + EPS_);
            out[(size_t)e * T_ + t] = inv2 * (Sg - m2 * S1) + C0;
        }
    }
}

extern "C" void kernel_launch(void* const* d_in, const int* in_sizes, int n_in,
                              void* d_out, int out_size) {
    const float* p[26];
    for (int i = 0; i < 26; i++) p[i] = (const float*)d_in[i];
    emb_pj_kernel<<<1024, 128>>>(p[0], p[1], p[2], p[3], p[4], p[5], p[6], p[7]);
    qlstm_kernel<<<1024, 64>>>(
        p[6], p[8], p[9], p[10], p[11], p[12], p[13],
        p[14], p[15], p[16], p[17], p[18], p[19], p[20], p[21],
        p[22], p[23], p[24], p[25], (float*)d_out);
}